// round 17
// baseline (speedup 1.0000x reference)
#include <cuda_runtime.h>
#include <cuda_bf16.h>
#include <cuda_fp16.h>
#include <math.h>

#define N_NODES 100000
#define E_EDGES 3200000
#define F_IN    256
#define F_HID   16
#define F_OUT   40

#define SCAN_BS 1024
#define SCAN_NB ((N_NODES + SCAN_BS - 1) / SCAN_BS)   // 98

#define NPB   128     // nodes per gather block (256 threads / 2 lanes)
#define CHUNK 4096    // smem edge-stage capacity (32 KB)

#define GEMM_BLOCKS ((N_NODES + 255) / 256)           // 391
#define EDGE_BLOCKS ((E_EDGES + 255) / 256)           // 12500

// -------- scratch (static device globals; 16B-aligned) ----------------------
__device__ __align__(16) float  g_deg   [N_NODES];
__device__ __align__(16) float  g_dinv  [N_NODES];
__device__ __align__(16) __half g_h1s   [N_NODES * F_HID];  // h1 * dinv (fp16)
__device__ __align__(16) __half g_r1s   [N_NODES * F_HID];  // relu(agg1+b1)*dinv
__device__ __align__(16) int2   g_rc    [E_EDGES];          // {row, col}
__device__ __align__(16) int    g_rank  [E_EDGES];          // rank within col bucket
__device__ __align__(16) int    g_cnt   [N_NODES];
__device__ __align__(16) int    g_ptr   [N_NODES + 1];
__device__ __align__(16) int2   g_sedge [E_EDGES];          // {row, bits(w)} sorted by col
__device__ __align__(16) int    g_bsum  [SCAN_NB];
__device__ int g_idx32 = 0;   // 1 => edge_index is int32, 0 => int64

// ---------------------------------------------------------------------------
// 1. node init; block 0 additionally detects edge_index dtype
// ---------------------------------------------------------------------------
__global__ void k_init_detect(const long long* __restrict__ ei) {
    int i = blockIdx.x * blockDim.x + threadIdx.x;
    if (i < N_NODES) { g_deg[i] = 1.0f; g_cnt[i] = 0; }

    if (blockIdx.x == 0) {
        __shared__ int s_or[8];
        int bad = 0;
#pragma unroll
        for (int q = 0; q < 16; q++) {
            long long v = ei[threadIdx.x + q * 256];
            if (v < 0 || v >= N_NODES) bad = 1;
        }
        bad = __any_sync(0xffffffffu, bad) ? 1 : 0;
        if ((threadIdx.x & 31) == 0) s_or[threadIdx.x >> 5] = bad;
        __syncthreads();
        if (threadIdx.x == 0) {
            int r = 0;
            for (int w = 0; w < 8; w++) r |= s_or[w];
            g_idx32 = r;
        }
    }
}

// ---------------------------------------------------------------------------
// 2. merged: blocks [0,GEMM_BLOCKS) -> h1 = x@W1 (fp32, scratch in g_sedge)
//            blocks [GEMM_BLOCKS,..) -> edge decode + histograms + rank
// ---------------------------------------------------------------------------
__global__ void __launch_bounds__(256)
k_edges_gemm(const void* __restrict__ ei, const float* __restrict__ ew,
             const float* __restrict__ x, const float* __restrict__ W1) {
    __shared__ float sW[F_IN * F_HID];   // 16 KB (gemm blocks only)

    if (blockIdx.x < GEMM_BLOCKS) {
        for (int i = threadIdx.x; i < F_IN * F_HID; i += blockDim.x)
            sW[i] = W1[i];
        __syncthreads();

        int node = blockIdx.x * 256 + threadIdx.x;
        if (node >= N_NODES) return;

        float acc[F_HID];
#pragma unroll
        for (int f = 0; f < F_HID; f++) acc[f] = 0.0f;

        const float4* xr = reinterpret_cast<const float4*>(x + (size_t)node * F_IN);
#pragma unroll 4
        for (int k4 = 0; k4 < F_IN / 4; k4++) {
            float4 xv = xr[k4];
            int kb = k4 * 4;
#pragma unroll
            for (int f = 0; f < F_HID; f++) {
                acc[f] = fmaf(xv.x, sW[(kb + 0) * F_HID + f], acc[f]);
                acc[f] = fmaf(xv.y, sW[(kb + 1) * F_HID + f], acc[f]);
                acc[f] = fmaf(xv.z, sW[(kb + 2) * F_HID + f], acc[f]);
                acc[f] = fmaf(xv.w, sW[(kb + 3) * F_HID + f], acc[f]);
            }
        }

        float4* h1o = reinterpret_cast<float4*>(g_sedge) + (size_t)node * 4;
#pragma unroll
        for (int q = 0; q < F_HID / 4; q++)
            h1o[q] = make_float4(acc[q*4+0], acc[q*4+1], acc[q*4+2], acc[q*4+3]);
    } else {
        int e = (blockIdx.x - GEMM_BLOCKS) * 256 + threadIdx.x;
        if (e >= E_EDGES) return;
        int row, col;
        if (g_idx32) {
            row = ((const int*)ei)[e];
            col = ((const int*)ei)[E_EDGES + e];
        } else {
            row = (int)((const long long*)ei)[e];
            col = (int)((const long long*)ei)[E_EDGES + e];
        }
        if ((unsigned)row >= (unsigned)N_NODES) row = 0;
        if ((unsigned)col >= (unsigned)N_NODES) col = 0;
        g_rc[e] = make_int2(row, col);
        atomicAdd(&g_deg[col], ew[e]);
        g_rank[e] = atomicAdd(&g_cnt[col], 1);   // rank within bucket, for free
    }
}

// ---------------------------------------------------------------------------
// 3. per-chunk exclusive scan of cnt (warp-shuffle) + dinv + h1s=h1*dinv
// ---------------------------------------------------------------------------
__global__ void __launch_bounds__(SCAN_BS)
k_scan_block() {
    __shared__ int ws[32];
    const unsigned FULL = 0xffffffffu;
    int tid  = threadIdx.x;
    int lane = tid & 31, wid = tid >> 5;
    int i = blockIdx.x * SCAN_BS + tid;

    int v = (i < N_NODES) ? g_cnt[i] : 0;

    if (i < N_NODES) {
        float d = g_deg[i];
        float di = (d > 0.0f) ? rsqrtf(d) : 0.0f;
        g_dinv[i] = di;
        const float4* h1i = reinterpret_cast<const float4*>(g_sedge) + (size_t)i * 4;
        uint2* ho = reinterpret_cast<uint2*>(g_h1s) + (size_t)i * 4;
#pragma unroll
        for (int q = 0; q < 4; q++) {
            float4 hv = h1i[q];
            __half2 lo = __floats2half2_rn(hv.x * di, hv.y * di);
            __half2 hi = __floats2half2_rn(hv.z * di, hv.w * di);
            uint2 pk;
            pk.x = *reinterpret_cast<unsigned*>(&lo);
            pk.y = *reinterpret_cast<unsigned*>(&hi);
            ho[q] = pk;
        }
    }

    int xv = v;
#pragma unroll
    for (int o = 1; o < 32; o <<= 1) {
        int t = __shfl_up_sync(FULL, xv, o);
        if (lane >= o) xv += t;
    }
    if (lane == 31) ws[wid] = xv;
    __syncthreads();
    if (wid == 0) {
        int y = ws[lane];
#pragma unroll
        for (int o = 1; o < 32; o <<= 1) {
            int t = __shfl_up_sync(FULL, y, o);
            if (lane >= o) y += t;
        }
        ws[lane] = y;
    }
    __syncthreads();
    int incl = xv + (wid > 0 ? ws[wid - 1] : 0);
    if (i < N_NODES) g_ptr[i] = incl - v;
    if (tid == SCAN_BS - 1) g_bsum[blockIdx.x] = incl;
}

// ---------------------------------------------------------------------------
// 4. add chunk offsets (each block redundantly scans the 98 chunk sums)
// ---------------------------------------------------------------------------
__global__ void k_scan_add() {
    __shared__ int sb[128];
    int tid = threadIdx.x;
    if (tid < 128) sb[tid] = (tid < SCAN_NB) ? g_bsum[tid] : 0;
    __syncthreads();
#pragma unroll
    for (int o = 1; o < 128; o <<= 1) {
        int t = (tid < 128 && tid >= o) ? sb[tid - o] : 0;
        __syncthreads();
        if (tid < 128) sb[tid] += t;
        __syncthreads();
    }
    int i = blockIdx.x * blockDim.x + tid;
    if (i < N_NODES) {
        int c = i >> 10;
        g_ptr[i] = g_ptr[i] + (c > 0 ? sb[c - 1] : 0);
    }
    if (i == 0) g_ptr[N_NODES] = E_EDGES;
}

// ---------------------------------------------------------------------------
// 5. CSR fill — NO atomics: pos = ptr[col] + rank
// ---------------------------------------------------------------------------
__global__ void k_fill(const float* __restrict__ ew) {
    int e = blockIdx.x * blockDim.x + threadIdx.x;
    if (e >= E_EDGES) return;
    int2 rc = g_rc[e];
    int pos = g_ptr[rc.y] + g_rank[e];
    g_sedge[pos] = make_int2(rc.x, __float_as_int(ew[e]));
}

// ---------------------------------------------------------------------------
// gather core: 2 lanes per node; lane q owns fp16 features [8q,8q+8) (uint4).
// acc_out = src[n] + sum_e w_e * src[row_e]   (values pre-scaled by dinv)
// ---------------------------------------------------------------------------
__device__ __forceinline__ void unpack_fma(float acc[8], uint4 pk, float w) {
    __half2 h0 = *reinterpret_cast<__half2*>(&pk.x);
    __half2 h1 = *reinterpret_cast<__half2*>(&pk.y);
    __half2 h2 = *reinterpret_cast<__half2*>(&pk.z);
    __half2 h3 = *reinterpret_cast<__half2*>(&pk.w);
    float2 a = __half22float2(h0), b = __half22float2(h1);
    float2 c = __half22float2(h2), d = __half22float2(h3);
    acc[0] = fmaf(a.x, w, acc[0]); acc[1] = fmaf(a.y, w, acc[1]);
    acc[2] = fmaf(b.x, w, acc[2]); acc[3] = fmaf(b.y, w, acc[3]);
    acc[4] = fmaf(c.x, w, acc[4]); acc[5] = fmaf(c.y, w, acc[5]);
    acc[6] = fmaf(d.x, w, acc[6]); acc[7] = fmaf(d.y, w, acc[7]);
}

__device__ __forceinline__ void load_h8(float acc[8], const uint4* src,
                                        int node, int q) {
    uint4 pk = src[node * 2 + q];
    __half2 h0 = *reinterpret_cast<__half2*>(&pk.x);
    __half2 h1 = *reinterpret_cast<__half2*>(&pk.y);
    __half2 h2 = *reinterpret_cast<__half2*>(&pk.z);
    __half2 h3 = *reinterpret_cast<__half2*>(&pk.w);
    float2 a = __half22float2(h0), b = __half22float2(h1);
    float2 c = __half22float2(h2), d = __half22float2(h3);
    acc[0] = a.x; acc[1] = a.y; acc[2] = b.x; acc[3] = b.y;
    acc[4] = c.x; acc[5] = c.y; acc[6] = d.x; acc[7] = d.y;
}

template <int LAYER>
__device__ __forceinline__ void gather_body(float acc[8], int node) {
    __shared__ int2 s_edges[CHUNK];

    const int q = threadIdx.x & 1;
    const uint4* src = reinterpret_cast<const uint4*>(LAYER == 0 ? g_h1s : g_r1s);

    int node_base = blockIdx.x * NPB;
    int last = min(node_base + NPB, N_NODES);

    int my_start = 0, my_end = 0;
    if (node < N_NODES) {
        my_start = g_ptr[node];
        my_end   = g_ptr[node + 1];
    }
    int blk_start = g_ptr[node_base];
    int blk_end   = g_ptr[last];

    for (int chunk = blk_start; chunk < blk_end; chunk += CHUNK) {
        int n = min(CHUNK, blk_end - chunk);
        __syncthreads();
        for (int i = threadIdx.x; i < n; i += blockDim.x)
            s_edges[i] = g_sedge[chunk + i];
        __syncthreads();

        int lo = max(my_start, chunk);
        int hi = min(my_end, chunk + n);
#pragma unroll 4
        for (int i = lo; i < hi; i++) {
            int2 e = s_edges[i - chunk];
            uint4 pk = src[e.x * 2 + q];
            unpack_fma(acc, pk, __int_as_float(e.y));
        }
    }
}

// layer-1: acc = h1s[n] + sum w*h1s[row]; r1s = relu(dinv*acc + b1) * dinv
__global__ void __launch_bounds__(256)
k_gather0(const float* __restrict__ b1) {
    int t = blockIdx.x * blockDim.x + threadIdx.x;
    int node = t >> 1;
    int q    = t & 1;

    float acc[8] = {0, 0, 0, 0, 0, 0, 0, 0};
    if (node < N_NODES)
        load_h8(acc, reinterpret_cast<const uint4*>(g_h1s), node, q);

    gather_body<0>(acc, node);

    if (node < N_NODES) {
        float di = g_dinv[node];
        float4 b_lo = reinterpret_cast<const float4*>(b1)[2 * q];
        float4 b_hi = reinterpret_cast<const float4*>(b1)[2 * q + 1];
        float r[8];
        r[0] = fmaxf(fmaf(acc[0], di, b_lo.x), 0.0f) * di;
        r[1] = fmaxf(fmaf(acc[1], di, b_lo.y), 0.0f) * di;
        r[2] = fmaxf(fmaf(acc[2], di, b_lo.z), 0.0f) * di;
        r[3] = fmaxf(fmaf(acc[3], di, b_lo.w), 0.0f) * di;
        r[4] = fmaxf(fmaf(acc[4], di, b_hi.x), 0.0f) * di;
        r[5] = fmaxf(fmaf(acc[5], di, b_hi.y), 0.0f) * di;
        r[6] = fmaxf(fmaf(acc[6], di, b_hi.z), 0.0f) * di;
        r[7] = fmaxf(fmaf(acc[7], di, b_hi.w), 0.0f) * di;
        __half2 p0 = __floats2half2_rn(r[0], r[1]);
        __half2 p1 = __floats2half2_rn(r[2], r[3]);
        __half2 p2 = __floats2half2_rn(r[4], r[5]);
        __half2 p3 = __floats2half2_rn(r[6], r[7]);
        uint4 pk;
        pk.x = *reinterpret_cast<unsigned*>(&p0);
        pk.y = *reinterpret_cast<unsigned*>(&p1);
        pk.z = *reinterpret_cast<unsigned*>(&p2);
        pk.w = *reinterpret_cast<unsigned*>(&p3);
        reinterpret_cast<uint4*>(g_r1s)[node * 2 + q] = pk;
    }
}

// layer-2: acc = r1s[n] + sum w*r1s[row]; agg2 = dinv*acc;
// projection (lane q -> cols [20q,20q+20)) + log_softmax; direct store
__global__ void __launch_bounds__(256)
k_gather1_final(const float* __restrict__ W2,
                const float* __restrict__ b2,
                float* __restrict__ out) {
    __shared__ float sW[F_HID * F_OUT];
    __shared__ float sb[F_OUT];
    for (int i = threadIdx.x; i < F_HID * F_OUT; i += blockDim.x) sW[i] = W2[i];
    for (int i = threadIdx.x; i < F_OUT; i += blockDim.x) sb[i] = b2[i];
    __syncthreads();

    int t = blockIdx.x * blockDim.x + threadIdx.x;
    int node = t >> 1;
    int q    = t & 1;

    float acc[8] = {0, 0, 0, 0, 0, 0, 0, 0};
    if (node < N_NODES)
        load_h8(acc, reinterpret_cast<const uint4*>(g_r1s), node, q);

    gather_body<1>(acc, node);

    if (node >= N_NODES) return;

    const unsigned FULL = 0xffffffffu;
    float di = g_dinv[node];
#pragma unroll
    for (int k = 0; k < 8; k++) acc[k] *= di;

    // assemble all 16 features on both lanes (pair swap via shfl_xor)
    float feat[16];
#pragma unroll
    for (int k = 0; k < 8; k++) {
        float oth = __shfl_xor_sync(FULL, acc[k], 1);
        feat[8 * q + k]       = acc[k];
        feat[8 * (1 - q) + k] = oth;
    }

    // projection: lane q computes contiguous cols [20q, 20q+20)
    float z[20];
    {
        const float4* sb4 = reinterpret_cast<const float4*>(sb) + 5 * q;
#pragma unroll
        for (int j5 = 0; j5 < 5; j5++) {
            float4 bv = sb4[j5];
            z[4*j5+0] = bv.x; z[4*j5+1] = bv.y; z[4*j5+2] = bv.z; z[4*j5+3] = bv.w;
        }
    }
    const float4* sW4 = reinterpret_cast<const float4*>(sW);
#pragma unroll
    for (int k = 0; k < F_HID; k++) {
        float fk = feat[k];
        int base = (k * F_OUT + 20 * q) >> 2;   // float4 index
#pragma unroll
        for (int j5 = 0; j5 < 5; j5++) {
            float4 wv = sW4[base + j5];
            z[4*j5+0] = fmaf(fk, wv.x, z[4*j5+0]);
            z[4*j5+1] = fmaf(fk, wv.y, z[4*j5+1]);
            z[4*j5+2] = fmaf(fk, wv.z, z[4*j5+2]);
            z[4*j5+3] = fmaf(fk, wv.w, z[4*j5+3]);
        }
    }

    // log_softmax over 40 cols (pair reduction)
    float m = z[0];
#pragma unroll
    for (int j = 1; j < 20; j++) m = fmaxf(m, z[j]);
    m = fmaxf(m, __shfl_xor_sync(FULL, m, 1));

    float se = 0.0f;
#pragma unroll
    for (int j = 0; j < 20; j++) se += expf(z[j] - m);
    se += __shfl_xor_sync(FULL, se, 1);
    float lse = m + logf(se);

    float4* op = reinterpret_cast<float4*>(out + (size_t)node * F_OUT + 20 * q);
#pragma unroll
    for (int j5 = 0; j5 < 5; j5++)
        op[j5] = make_float4(z[4*j5+0] - lse, z[4*j5+1] - lse,
                             z[4*j5+2] - lse, z[4*j5+3] - lse);
}

// ---------------------------------------------------------------------------
// launch — 7 kernels
// ---------------------------------------------------------------------------
extern "C" void kernel_launch(void* const* d_in, const int* in_sizes, int n_in,
                              void* d_out, int out_size) {
    const float* x  = nullptr;
    const void*  ei = nullptr;
    const float* ew = nullptr;
    const float* W1 = nullptr;
    const float* b1 = nullptr;
    const float* W2 = nullptr;
    const float* b2 = nullptr;

    for (int i = 0; i < n_in; i++) {
        switch (in_sizes[i]) {
            case N_NODES * F_IN:   x  = (const float*)d_in[i]; break;
            case 2 * E_EDGES:      ei = d_in[i];               break;
            case E_EDGES:          ew = (const float*)d_in[i]; break;
            case F_IN * F_HID:     W1 = (const float*)d_in[i]; break;
            case F_HID:            b1 = (const float*)d_in[i]; break;
            case F_HID * F_OUT:    W2 = (const float*)d_in[i]; break;
            case F_OUT:            b2 = (const float*)d_in[i]; break;
            default: break;
        }
    }
    float* out = (float*)d_out;

    const int T  = 256;
    const int GE = (E_EDGES + T - 1) / T;
    const int GN = (N_NODES + T - 1) / T;
    const int GG = (N_NODES + NPB - 1) / NPB;

    k_init_detect<<<GN, T>>>((const long long*)ei);
    k_edges_gemm<<<GEMM_BLOCKS + EDGE_BLOCKS, T>>>(ei, ew, x, W1);
    k_scan_block<<<SCAN_NB, SCAN_BS>>>();
    k_scan_add<<<GN, T>>>();
    k_fill<<<GE, T>>>(ew);
    k_gather0<<<GG, T>>>(b1);
    k_gather1_final<<<GG, T>>>(W2, b2, out);
}